// round 3
// baseline (speedup 1.0000x reference)
#include <cuda_runtime.h>
#include <math.h>

// Problem shape (fixed by the dataset instance)
constexpr int Bb = 2, Ts = 2048, E = 1024, Hh = 16, Dd = 64, Ff = 4096;
constexpr int Mrows = Bb * Ts;   // 4096

// ---------------- scratch (device globals; no allocation allowed) ----------
__device__ float g_h  [(size_t)Mrows * E];       // LN1 output
__device__ float g_proj[(size_t)Mrows * 3 * E];  // QKV projection
__device__ float g_q  [(size_t)Mrows * E];       // [B,H,T,D]
__device__ float g_k  [(size_t)Mrows * E];       // [B,H,T,D]
__device__ float g_v  [(size_t)Mrows * E];       // [B,H,T,D]
__device__ float g_o  [(size_t)Mrows * E];       // attn out, [B,T,H*D]
__device__ float g_x1 [(size_t)Mrows * E];       // x + o@Wo^T
__device__ float g_h2 [(size_t)Mrows * E];       // LN2 output
__device__ float g_f1 [(size_t)Mrows * Ff];      // gelu(h2@w1^T)

// ---------------- LayerNorm: one block per row ------------------------------
__global__ void __launch_bounds__(256) ln_kernel(
    const float* __restrict__ x, const float* __restrict__ g,
    const float* __restrict__ bta, float* __restrict__ out)
{
    int row = blockIdx.x;
    const float* xr = x + (size_t)row * E;
    float s = 0.f, s2 = 0.f;
    for (int i = threadIdx.x; i < E; i += 256) {
        float v = xr[i];
        s += v; s2 += v * v;
    }
    #pragma unroll
    for (int o = 16; o; o >>= 1) {
        s  += __shfl_xor_sync(0xffffffffu, s,  o);
        s2 += __shfl_xor_sync(0xffffffffu, s2, o);
    }
    __shared__ float sh[2][8];
    int w = threadIdx.x >> 5, ln = threadIdx.x & 31;
    if (ln == 0) { sh[0][w] = s; sh[1][w] = s2; }
    __syncthreads();
    float ts = 0.f, ts2 = 0.f;
    #pragma unroll
    for (int i = 0; i < 8; i++) { ts += sh[0][i]; ts2 += sh[1][i]; }
    float mu  = ts  * (1.f / E);
    float var = ts2 * (1.f / E) - mu * mu;
    float rs  = rsqrtf(var + 1e-5f);
    float* orow = out + (size_t)row * E;
    for (int i = threadIdx.x; i < E; i += 256)
        orow[i] = (xr[i] - mu) * rs * g[i] + bta[i];
}

// ---------------- RoPE split: proj -> q,k (roped, [B,H,T,D]) + v ------------
__global__ void __launch_bounds__(256) rope_kernel(const float* __restrict__ proj)
{
    int idx = blockIdx.x * 256 + threadIdx.x;  // Bb*Ts*Hh*32 threads
    int i = idx & 31;                 // rotary pair index (half = 32)
    int h = (idx >> 5) & 15;
    int t = (idx >> 9) & (Ts - 1);
    int b = idx >> 20;
    if (b >= Bb) return;
    size_t base = ((size_t)(b * Ts + t) * 3) * E + (size_t)h * Dd + 2 * i;
    float qr = proj[base],         qi = proj[base + 1];
    float kr = proj[base + E],     ki = proj[base + E + 1];
    float vr = proj[base + 2 * E], vi = proj[base + 2 * E + 1];
    double invf = pow(10000.0, -(double)i / 32.0);
    double ang  = (double)t * invf;
    float c = (float)cos(ang), sn = (float)sin(ang);
    size_t ob = ((size_t)(b * Hh + h) * Ts + t) * Dd + 2 * i;
    g_q[ob]     = qr * c - qi * sn;
    g_q[ob + 1] = qr * sn + qi * c;
    g_k[ob]     = kr * c - ki * sn;
    g_k[ob + 1] = kr * sn + ki * c;
    g_v[ob]     = vr;
    g_v[ob + 1] = vi;
}

// ---------------- Sliding-window attention (flash-style) --------------------
// Block: (b,h) x 32-query tile; 256 threads = 32 queries x 8 threads.
// Each thread owns 8 d-dims of one query's accumulator.
// Static shared memory only (~30 KB) — no dynamic smem, no attribute calls.
constexpr int QT = 32, KC = 32;

__global__ void __launch_bounds__(256) attn_kernel(const int* __restrict__ ctx)
{
    __shared__ float qs[QT][68];
    __shared__ float ks[KC][68];
    __shared__ float vs[KC][68];
    __shared__ float sc[QT][KC + 1];

    int W  = *ctx;
    int bh = blockIdx.y;                 // b*H + h
    int t0 = blockIdx.x * QT;
    const float* qb = g_q + (size_t)bh * Ts * Dd;
    const float* kb = g_k + (size_t)bh * Ts * Dd;
    const float* vb = g_v + (size_t)bh * Ts * Dd;
    int tid = threadIdx.x;

    // Load Q tile (32 x 64 floats)
    {
        int c = tid & 15, r0 = tid >> 4;
        #pragma unroll
        for (int rr = 0; rr < 2; rr++) {
            int r = r0 + rr * 16;
            float4 v4 = *(const float4*)(qb + (size_t)(t0 + r) * Dd + c * 4);
            *(float4*)(&qs[r][c * 4]) = v4;
        }
    }

    int qi = tid >> 3, l8 = tid & 7;
    int t  = t0 + qi;
    int d0 = l8 * 8;
    float m = -1e30f, l = 0.f;
    float acc[8];
    #pragma unroll
    for (int dd = 0; dd < 8; dd++) acc[dd] = 0.f;

    int s_lo = t0 - W + 1; if (s_lo < 0) s_lo = 0;
    int s_hi = t0 + QT - 1; if (s_hi > Ts - 1) s_hi = Ts - 1;

    for (int cs = s_lo; cs <= s_hi; cs += KC) {
        __syncthreads();   // protect previous chunk's ks/vs reads
        {
            int c = tid & 15, r = tid >> 4;  // 16 rows per pass, 2 passes
            #pragma unroll
            for (int rr = 0; rr < 2; rr++) {
                int r2 = r + rr * 16;
                int s = cs + r2;
                float4 kv = make_float4(0.f, 0.f, 0.f, 0.f), vv = kv;
                if (s <= s_hi) {
                    kv = *(const float4*)(kb + (size_t)s * Dd + c * 4);
                    vv = *(const float4*)(vb + (size_t)s * Dd + c * 4);
                }
                *(float4*)(&ks[r2][c * 4]) = kv;
                *(float4*)(&vs[r2][c * 4]) = vv;
            }
        }
        __syncthreads();

        // scores: each thread computes 4 keys (jj = l8 + 8*kk) for its query
        float dot[4];
        #pragma unroll
        for (int kk = 0; kk < 4; kk++) dot[kk] = 0.f;
        #pragma unroll
        for (int d = 0; d < Dd; d++) {
            float qv = qs[qi][d];
            #pragma unroll
            for (int kk = 0; kk < 4; kk++)
                dot[kk] += qv * ks[l8 + kk * 8][d];
        }
        #pragma unroll
        for (int kk = 0; kk < 4; kk++) {
            int jj = l8 + kk * 8;
            int s  = cs + jj;
            bool valid = (s <= t) && (t - s < W) && (s <= s_hi);
            sc[qi][jj] = valid ? dot[kk] * 0.125f : -1e30f;
        }
        __syncwarp();

        float cm = -1e30f;
        #pragma unroll
        for (int j = 0; j < KC; j++) cm = fmaxf(cm, sc[qi][j]);
        if (cm > -1e29f) {   // chunk has at least one valid key
            float nm   = fmaxf(m, cm);
            float corr = __expf(m - nm);
            l *= corr;
            #pragma unroll
            for (int dd = 0; dd < 8; dd++) acc[dd] *= corr;
            #pragma unroll
            for (int j = 0; j < KC; j++) {
                float p = __expf(sc[qi][j] - nm);
                l += p;
                #pragma unroll
                for (int dd = 0; dd < 8; dd++)
                    acc[dd] += p * vs[j][d0 + dd];
            }
            m = nm;
        }
        __syncwarp();
    }

    float inv = 1.f / l;
    int b = bh >> 4, h = bh & 15;
    float* op = g_o + ((size_t)(b * Ts + t) * Hh + h) * Dd + d0;
    #pragma unroll
    for (int dd = 0; dd < 8; dd++) op[dd] = acc[dd] * inv;
}

// ---------------- SGEMM (NT): C[m,n] = epi( sum_k A[m,k]*B[n,k] [+ R[m,n]] )
// 128x128 tile, BK=8, 256 threads, 8x8 per thread. Dims must be /128 (/8 for K).
// EPI: 0=none, 1=exact GELU, 2=residual add
template <int EPI>
__global__ void __launch_bounds__(256) gemm_nt(
    const float* __restrict__ A, const float* __restrict__ Bw,
    const float* __restrict__ R, float* __restrict__ C,
    int Mn, int Nn, int Kn)
{
    __shared__ float As[8][128];
    __shared__ float Bs[8][128];
    int bm = blockIdx.y * 128, bn = blockIdx.x * 128;
    int tid = threadIdx.x;
    int lrow = tid >> 1;
    int lcol = (tid & 1) << 2;
    int tx = tid & 15, ty = tid >> 4;

    float acc[8][8];
    #pragma unroll
    for (int i = 0; i < 8; i++)
        #pragma unroll
        for (int j = 0; j < 8; j++) acc[i][j] = 0.f;

    const float* Ap = A  + (size_t)(bm + lrow) * Kn + lcol;
    const float* Bp = Bw + (size_t)(bn + lrow) * Kn + lcol;

    for (int k0 = 0; k0 < Kn; k0 += 8) {
        float4 av = *(const float4*)(Ap + k0);
        float4 bv = *(const float4*)(Bp + k0);
        __syncthreads();
        As[lcol + 0][lrow] = av.x; As[lcol + 1][lrow] = av.y;
        As[lcol + 2][lrow] = av.z; As[lcol + 3][lrow] = av.w;
        Bs[lcol + 0][lrow] = bv.x; Bs[lcol + 1][lrow] = bv.y;
        Bs[lcol + 2][lrow] = bv.z; Bs[lcol + 3][lrow] = bv.w;
        __syncthreads();
        #pragma unroll
        for (int k = 0; k < 8; k++) {
            float ar[8], br[8];
            *(float4*)(ar)     = *(const float4*)(&As[k][ty * 4]);
            *(float4*)(ar + 4) = *(const float4*)(&As[k][64 + ty * 4]);
            *(float4*)(br)     = *(const float4*)(&Bs[k][tx * 4]);
            *(float4*)(br + 4) = *(const float4*)(&Bs[k][64 + tx * 4]);
            #pragma unroll
            for (int i = 0; i < 8; i++)
                #pragma unroll
                for (int j = 0; j < 8; j++)
                    acc[i][j] += ar[i] * br[j];
        }
    }

    #pragma unroll
    for (int i = 0; i < 8; i++) {
        int m = bm + ((i < 4) ? (ty * 4 + i) : (64 + ty * 4 + i - 4));
        #pragma unroll
        for (int js = 0; js < 2; js++) {
            int n = bn + js * 64 + tx * 4;
            float vals[4];
            #pragma unroll
            for (int j = 0; j < 4; j++) {
                float v = acc[i][js * 4 + j];
                if (EPI == 1)
                    v = 0.5f * v * (1.f + erff(v * 0.70710678118654752f));
                vals[j] = v;
            }
            if (EPI == 2) {
                float4 rv = *(const float4*)(R + (size_t)m * Nn + n);
                vals[0] += rv.x; vals[1] += rv.y;
                vals[2] += rv.z; vals[3] += rv.w;
            }
            *(float4*)(C + (size_t)m * Nn + n) =
                make_float4(vals[0], vals[1], vals[2], vals[3]);
        }
    }
}

// ---------------- launch ----------------------------------------------------
extern "C" void kernel_launch(void* const* d_in, const int* in_sizes, int n_in,
                              void* d_out, int out_size)
{
    (void)in_sizes; (void)n_in; (void)out_size;
    const float* x    = (const float*)d_in[0];
    const float* wqkv = (const float*)d_in[1];
    const float* wo   = (const float*)d_in[2];
    const float* g1   = (const float*)d_in[3];
    const float* b1   = (const float*)d_in[4];
    const float* g2   = (const float*)d_in[5];
    const float* b2   = (const float*)d_in[6];
    const float* w1   = (const float*)d_in[7];
    const float* w2   = (const float*)d_in[8];
    const int*   ctx  = (const int*)  d_in[9];
    float* out = (float*)d_out;

    float *h, *proj, *o, *x1, *h2, *f1;
    cudaGetSymbolAddress((void**)&h,    g_h);
    cudaGetSymbolAddress((void**)&proj, g_proj);
    cudaGetSymbolAddress((void**)&o,    g_o);
    cudaGetSymbolAddress((void**)&x1,   g_x1);
    cudaGetSymbolAddress((void**)&h2,   g_h2);
    cudaGetSymbolAddress((void**)&f1,   g_f1);

    // 1) LN1
    ln_kernel<<<Mrows, 256>>>(x, g1, b1, h);
    // 2) QKV projection: [4096,1024] x [3072,1024]^T
    gemm_nt<0><<<dim3(3 * E / 128, Mrows / 128), 256>>>(h, wqkv, nullptr, proj,
                                                        Mrows, 3 * E, E);
    // 3) RoPE + split to [B,H,T,D]
    rope_kernel<<<(Bb * Ts * Hh * 32) / 256, 256>>>(proj);
    // 4) Sliding-window attention
    attn_kernel<<<dim3(Ts / QT, Bb * Hh), 256>>>(ctx);
    // 5) out-proj + residual
    gemm_nt<2><<<dim3(E / 128, Mrows / 128), 256>>>(o, wo, x, x1,
                                                    Mrows, E, E);
    // 6) LN2
    ln_kernel<<<Mrows, 256>>>(x1, g2, b2, h2);
    // 7) FFN up + exact GELU
    gemm_nt<1><<<dim3(Ff / 128, Mrows / 128), 256>>>(h2, w1, nullptr, f1,
                                                     Mrows, Ff, E);
    // 8) FFN down + residual -> output
    gemm_nt<2><<<dim3(E / 128, Mrows / 128), 256>>>(f1, w2, x1, out,
                                                    Mrows, E, Ff);
}

// round 7
// speedup vs baseline: 1.3564x; 1.3564x over previous
#include <cuda_runtime.h>
#include <cuda_bf16.h>
#include <cstdint>
#include <math.h>

// Problem shape (fixed by the dataset instance)
constexpr int Bb = 2, Ts = 2048, E = 1024, Hh = 16, Dd = 64, Ff = 4096;
constexpr int Mrows = Bb * Ts;   // 4096

// ---------------- scratch (device globals; no allocation allowed) ----------
__device__ float g_h  [(size_t)Mrows * E];       // LN1 output
__device__ float g_proj[(size_t)Mrows * 3 * E];  // QKV projection
__device__ float g_q  [(size_t)Mrows * E];       // [B,H,T,D]
__device__ float g_k  [(size_t)Mrows * E];       // [B,H,T,D]
__device__ float g_v  [(size_t)Mrows * E];       // [B,H,T,D]
__device__ float g_o  [(size_t)Mrows * E];       // attn out, [B,T,H*D]
__device__ float g_x1 [(size_t)Mrows * E];       // x + o@Wo^T
__device__ float g_h2 [(size_t)Mrows * E];       // LN2 output
__device__ float g_f1 [(size_t)Mrows * Ff];      // gelu(h2@w1^T)

// ---------------- LayerNorm: one block per row ------------------------------
__global__ void __launch_bounds__(256) ln_kernel(
    const float* __restrict__ x, const float* __restrict__ g,
    const float* __restrict__ bta, float* __restrict__ out)
{
    int row = blockIdx.x;
    const float* xr = x + (size_t)row * E;
    float s = 0.f, s2 = 0.f;
    for (int i = threadIdx.x; i < E; i += 256) {
        float v = xr[i];
        s += v; s2 += v * v;
    }
    #pragma unroll
    for (int o = 16; o; o >>= 1) {
        s  += __shfl_xor_sync(0xffffffffu, s,  o);
        s2 += __shfl_xor_sync(0xffffffffu, s2, o);
    }
    __shared__ float sh[2][8];
    int w = threadIdx.x >> 5, ln = threadIdx.x & 31;
    if (ln == 0) { sh[0][w] = s; sh[1][w] = s2; }
    __syncthreads();
    float ts = 0.f, ts2 = 0.f;
    #pragma unroll
    for (int i = 0; i < 8; i++) { ts += sh[0][i]; ts2 += sh[1][i]; }
    float mu  = ts  * (1.f / E);
    float var = ts2 * (1.f / E) - mu * mu;
    float rs  = rsqrtf(var + 1e-5f);
    float* orow = out + (size_t)row * E;
    for (int i = threadIdx.x; i < E; i += 256)
        orow[i] = (xr[i] - mu) * rs * g[i] + bta[i];
}

// ---------------- RoPE split: proj -> q,k (roped, [B,H,T,D]) + v ------------
__global__ void __launch_bounds__(256) rope_kernel(const float* __restrict__ proj)
{
    int idx = blockIdx.x * 256 + threadIdx.x;  // Bb*Ts*Hh*32 threads
    int i = idx & 31;                 // rotary pair index (half = 32)
    int h = (idx >> 5) & 15;
    int t = (idx >> 9) & (Ts - 1);
    int b = idx >> 20;
    if (b >= Bb) return;
    size_t base = ((size_t)(b * Ts + t) * 3) * E + (size_t)h * Dd + 2 * i;
    float qr = proj[base],         qi = proj[base + 1];
    float kr = proj[base + E],     ki = proj[base + E + 1];
    float vr = proj[base + 2 * E], vi = proj[base + 2 * E + 1];
    double invf = pow(10000.0, -(double)i / 32.0);
    double ang  = (double)t * invf;
    float c = (float)cos(ang), sn = (float)sin(ang);
    size_t ob = ((size_t)(b * Hh + h) * Ts + t) * Dd + 2 * i;
    g_q[ob]     = qr * c - qi * sn;
    g_q[ob + 1] = qr * sn + qi * c;
    g_k[ob]     = kr * c - ki * sn;
    g_k[ob + 1] = kr * sn + ki * c;
    g_v[ob]     = vr;
    g_v[ob + 1] = vi;
}

// ---------------- Sliding-window attention (flash-style) --------------------
constexpr int QT = 32, KC = 32;

__global__ void __launch_bounds__(256) attn_kernel(const int* __restrict__ ctx)
{
    __shared__ float qs[QT][68];
    __shared__ float ks[KC][68];
    __shared__ float vs[KC][68];
    __shared__ float sc[QT][KC + 1];

    int W  = *ctx;
    int bh = blockIdx.y;                 // b*H + h
    int t0 = blockIdx.x * QT;
    const float* qb = g_q + (size_t)bh * Ts * Dd;
    const float* kb = g_k + (size_t)bh * Ts * Dd;
    const float* vb = g_v + (size_t)bh * Ts * Dd;
    int tid = threadIdx.x;

    // Load Q tile (32 x 64 floats)
    {
        int c = tid & 15, r0 = tid >> 4;
        #pragma unroll
        for (int rr = 0; rr < 2; rr++) {
            int r = r0 + rr * 16;
            float4 v4 = *(const float4*)(qb + (size_t)(t0 + r) * Dd + c * 4);
            *(float4*)(&qs[r][c * 4]) = v4;
        }
    }

    int qi = tid >> 3, l8 = tid & 7;
    int t  = t0 + qi;
    int d0 = l8 * 8;
    float m = -1e30f, l = 0.f;
    float acc[8];
    #pragma unroll
    for (int dd = 0; dd < 8; dd++) acc[dd] = 0.f;

    int s_lo = t0 - W + 1; if (s_lo < 0) s_lo = 0;
    int s_hi = t0 + QT - 1; if (s_hi > Ts - 1) s_hi = Ts - 1;

    for (int cs = s_lo; cs <= s_hi; cs += KC) {
        __syncthreads();   // protect previous chunk's ks/vs reads
        {
            int c = tid & 15, r = tid >> 4;  // 16 rows per pass, 2 passes
            #pragma unroll
            for (int rr = 0; rr < 2; rr++) {
                int r2 = r + rr * 16;
                int s = cs + r2;
                float4 kv = make_float4(0.f, 0.f, 0.f, 0.f), vv = kv;
                if (s <= s_hi) {
                    kv = *(const float4*)(kb + (size_t)s * Dd + c * 4);
                    vv = *(const float4*)(vb + (size_t)s * Dd + c * 4);
                }
                *(float4*)(&ks[r2][c * 4]) = kv;
                *(float4*)(&vs[r2][c * 4]) = vv;
            }
        }
        __syncthreads();

        // scores: each thread computes 4 keys (jj = l8 + 8*kk) for its query
        float dot[4];
        #pragma unroll
        for (int kk = 0; kk < 4; kk++) dot[kk] = 0.f;
        #pragma unroll
        for (int d = 0; d < Dd; d++) {
            float qv = qs[qi][d];
            #pragma unroll
            for (int kk = 0; kk < 4; kk++)
                dot[kk] += qv * ks[l8 + kk * 8][d];
        }
        #pragma unroll
        for (int kk = 0; kk < 4; kk++) {
            int jj = l8 + kk * 8;
            int s  = cs + jj;
            bool valid = (s <= t) && (t - s < W) && (s <= s_hi);
            sc[qi][jj] = valid ? dot[kk] * 0.125f : -1e30f;
        }
        __syncwarp();

        float cm = -1e30f;
        #pragma unroll
        for (int j = 0; j < KC; j++) cm = fmaxf(cm, sc[qi][j]);
        if (cm > -1e29f) {   // chunk has at least one valid key
            float nm   = fmaxf(m, cm);
            float corr = __expf(m - nm);
            l *= corr;
            #pragma unroll
            for (int dd = 0; dd < 8; dd++) acc[dd] *= corr;
            #pragma unroll
            for (int j = 0; j < KC; j++) {
                float p = __expf(sc[qi][j] - nm);
                l += p;
                #pragma unroll
                for (int dd = 0; dd < 8; dd++)
                    acc[dd] += p * vs[j][d0 + dd];
            }
            m = nm;
        }
        __syncwarp();
    }

    float inv = 1.f / l;
    int b = bh >> 4, h = bh & 15;
    float* op = g_o + ((size_t)(b * Ts + t) * Hh + h) * Dd + d0;
    #pragma unroll
    for (int dd = 0; dd < 8; dd++) op[dd] = acc[dd] * inv;
}

// ---------------- Tensor-core GEMM (NT), bf16x3 split for fp32 accuracy -----
// C[m,n] = epi( sum_k A[m,k]*B[n,k] [+ R[m,n]] )
// 128x128 tile, BK=16, 256 threads (8 warps, 2x4), 64x32 warp tile.
// a = a_hi + a_lo (bf16); computes ah*bh + ah*bl + al*bh, fp32 accumulate.
// EPI: 0=none, 1=exact GELU, 2=residual add
constexpr int BK   = 16;
constexpr int LDSB = BK + 8;   // bf16 row stride (24 -> 48B, conflict-free)

__device__ __forceinline__ uint32_t pack_bf2(__nv_bfloat16 lo, __nv_bfloat16 hi)
{
    uint16_t l = *reinterpret_cast<uint16_t*>(&lo);
    uint16_t h = *reinterpret_cast<uint16_t*>(&hi);
    return ((uint32_t)h << 16) | l;
}

#define MMA_BF16(c, a0, a1, a2, a3, b0, b1)                                   \
    asm volatile(                                                             \
        "mma.sync.aligned.m16n8k16.row.col.f32.bf16.bf16.f32 "                \
        "{%0,%1,%2,%3}, {%4,%5,%6,%7}, {%8,%9}, {%0,%1,%2,%3};\n"             \
        : "+f"(c[0]), "+f"(c[1]), "+f"(c[2]), "+f"(c[3])                      \
        : "r"(a0), "r"(a1), "r"(a2), "r"(a3), "r"(b0), "r"(b1))

template <int EPI>
__global__ void __launch_bounds__(256) gemm_nt_mma(
    const float* __restrict__ A, const float* __restrict__ Bw,
    const float* __restrict__ R, float* __restrict__ C,
    int Mn, int Nn, int Kn)
{
    __shared__ __nv_bfloat16 As[2][2][128 * LDSB];  // [buf][hi=0/lo=1]
    __shared__ __nv_bfloat16 Bs[2][2][128 * LDSB];

    int tid  = threadIdx.x;
    int warp = tid >> 5, lane = tid & 31;
    int wm = warp >> 2, wn = warp & 3;       // 2 x 4 warp grid
    int g  = lane >> 2, cq = lane & 3;       // fragment row group / k-quad

    int bm = blockIdx.y * 128, bn = blockIdx.x * 128;

    // gmem staging: each thread loads 8 floats of A and 8 of B per k-step
    int ldrow = tid >> 1;
    int ldcol = (tid & 1) * 8;
    const float* Ag = A  + (size_t)(bm + ldrow) * Kn + ldcol;
    const float* Bg = Bw + (size_t)(bn + ldrow) * Kn + ldcol;

    float acc[4][4][4];
    #pragma unroll
    for (int i = 0; i < 4; i++)
        #pragma unroll
        for (int j = 0; j < 4; j++)
            #pragma unroll
            for (int c = 0; c < 4; c++) acc[i][j][c] = 0.f;

    float ra[8], rb[8];

    auto fetch = [&](int k0) {
        *(float4*)(ra)     = *(const float4*)(Ag + k0);
        *(float4*)(ra + 4) = *(const float4*)(Ag + k0 + 4);
        *(float4*)(rb)     = *(const float4*)(Bg + k0);
        *(float4*)(rb + 4) = *(const float4*)(Bg + k0 + 4);
    };

    auto stage = [&](int buf) {
        uint32_t ah[4], al[4], bh[4], bl[4];
        #pragma unroll
        for (int i = 0; i < 4; i++) {
            float a0 = ra[2 * i], a1 = ra[2 * i + 1];
            __nv_bfloat16 h0 = __float2bfloat16(a0);
            __nv_bfloat16 h1 = __float2bfloat16(a1);
            __nv_bfloat16 l0 = __float2bfloat16(a0 - __bfloat162float(h0));
            __nv_bfloat16 l1 = __float2bfloat16(a1 - __bfloat162float(h1));
            ah[i] = pack_bf2(h0, h1);
            al[i] = pack_bf2(l0, l1);
            float b0 = rb[2 * i], b1 = rb[2 * i + 1];
            __nv_bfloat16 p0 = __float2bfloat16(b0);
            __nv_bfloat16 p1 = __float2bfloat16(b1);
            __nv_bfloat16 q0 = __float2bfloat16(b0 - __bfloat162float(p0));
            __nv_bfloat16 q1 = __float2bfloat16(b1 - __bfloat162float(p1));
            bh[i] = pack_bf2(p0, p1);
            bl[i] = pack_bf2(q0, q1);
        }
        int off = ldrow * LDSB + ldcol;
        *(uint4*)(&As[buf][0][off]) = make_uint4(ah[0], ah[1], ah[2], ah[3]);
        *(uint4*)(&As[buf][1][off]) = make_uint4(al[0], al[1], al[2], al[3]);
        *(uint4*)(&Bs[buf][0][off]) = make_uint4(bh[0], bh[1], bh[2], bh[3]);
        *(uint4*)(&Bs[buf][1][off]) = make_uint4(bl[0], bl[1], bl[2], bl[3]);
    };

    int nk = Kn / BK;
    fetch(0);
    stage(0);
    int buf = 0;

    for (int ks = 0; ks < nk; ks++) {
        __syncthreads();
        if (ks + 1 < nk) fetch((ks + 1) * BK);

        const __nv_bfloat16* ash = As[buf][0];
        const __nv_bfloat16* asl = As[buf][1];
        const __nv_bfloat16* bsh = Bs[buf][0];
        const __nv_bfloat16* bsl = Bs[buf][1];

        // A fragments for 4 m-tiles (hi and lo)
        uint32_t afh[4][4], afl[4][4];
        #pragma unroll
        for (int mt = 0; mt < 4; mt++) {
            int r0 = (wm * 64 + mt * 16 + g) * LDSB + 2 * cq;
            int r8 = r0 + 8 * LDSB;
            afh[mt][0] = *(const uint32_t*)(ash + r0);
            afh[mt][1] = *(const uint32_t*)(ash + r8);
            afh[mt][2] = *(const uint32_t*)(ash + r0 + 8);
            afh[mt][3] = *(const uint32_t*)(ash + r8 + 8);
            afl[mt][0] = *(const uint32_t*)(asl + r0);
            afl[mt][1] = *(const uint32_t*)(asl + r8);
            afl[mt][2] = *(const uint32_t*)(asl + r0 + 8);
            afl[mt][3] = *(const uint32_t*)(asl + r8 + 8);
        }

        #pragma unroll
        for (int nt = 0; nt < 4; nt++) {
            int n0 = (wn * 32 + nt * 8 + g) * LDSB + 2 * cq;
            uint32_t bfh0 = *(const uint32_t*)(bsh + n0);
            uint32_t bfh1 = *(const uint32_t*)(bsh + n0 + 8);
            uint32_t bfl0 = *(const uint32_t*)(bsl + n0);
            uint32_t bfl1 = *(const uint32_t*)(bsl + n0 + 8);
            #pragma unroll
            for (int mt = 0; mt < 4; mt++) {
                MMA_BF16(acc[mt][nt], afh[mt][0], afh[mt][1], afh[mt][2],
                         afh[mt][3], bfh0, bfh1);
                MMA_BF16(acc[mt][nt], afh[mt][0], afh[mt][1], afh[mt][2],
                         afh[mt][3], bfl0, bfl1);
                MMA_BF16(acc[mt][nt], afl[mt][0], afl[mt][1], afl[mt][2],
                         afl[mt][3], bfh0, bfh1);
            }
        }

        if (ks + 1 < nk) { stage(buf ^ 1); buf ^= 1; }
    }

    // Epilogue: each thread owns (c0,c1)@row g and (c2,c3)@row g+8 per tile
    #pragma unroll
    for (int mt = 0; mt < 4; mt++) {
        #pragma unroll
        for (int half = 0; half < 2; half++) {
            int r = bm + wm * 64 + mt * 16 + g + half * 8;
            #pragma unroll
            for (int nt = 0; nt < 4; nt++) {
                int ncol = bn + wn * 32 + nt * 8 + 2 * cq;
                float v0 = acc[mt][nt][half * 2 + 0];
                float v1 = acc[mt][nt][half * 2 + 1];
                if (EPI == 1) {
                    v0 = 0.5f * v0 * (1.f + erff(v0 * 0.70710678118654752f));
                    v1 = 0.5f * v1 * (1.f + erff(v1 * 0.70710678118654752f));
                }
                if (EPI == 2) {
                    float2 rv = *(const float2*)(R + (size_t)r * Nn + ncol);
                    v0 += rv.x; v1 += rv.y;
                }
                *(float2*)(C + (size_t)r * Nn + ncol) = make_float2(v0, v1);
            }
        }
    }
}

// ---------------- launch ----------------------------------------------------
extern "C" void kernel_launch(void* const* d_in, const int* in_sizes, int n_in,
                              void* d_out, int out_size)
{
    (void)in_sizes; (void)n_in; (void)out_size;
    const float* x    = (const float*)d_in[0];
    const float* wqkv = (const float*)d_in[1];
    const float* wo   = (const float*)d_in[2];
    const float* g1   = (const float*)d_in[3];
    const float* b1   = (const float*)d_in[4];
    const float* g2   = (const float*)d_in[5];
    const float* b2   = (const float*)d_in[6];
    const float* w1   = (const float*)d_in[7];
    const float* w2   = (const float*)d_in[8];
    const int*   ctx  = (const int*)  d_in[9];
    float* out = (float*)d_out;

    float *h, *proj, *o, *x1, *h2, *f1;
    cudaGetSymbolAddress((void**)&h,    g_h);
    cudaGetSymbolAddress((void**)&proj, g_proj);
    cudaGetSymbolAddress((void**)&o,    g_o);
    cudaGetSymbolAddress((void**)&x1,   g_x1);
    cudaGetSymbolAddress((void**)&h2,   g_h2);
    cudaGetSymbolAddress((void**)&f1,   g_f1);

    // 1) LN1
    ln_kernel<<<Mrows, 256>>>(x, g1, b1, h);
    // 2) QKV projection: [4096,1024] x [3072,1024]^T
    gemm_nt_mma<0><<<dim3(3 * E / 128, Mrows / 128), 256>>>(h, wqkv, nullptr,
                                                            proj, Mrows, 3 * E, E);
    // 3) RoPE + split to [B,H,T,D]
    rope_kernel<<<(Bb * Ts * Hh * 32) / 256, 256>>>(proj);
    // 4) Sliding-window attention
    attn_kernel<<<dim3(Ts / QT, Bb * Hh), 256>>>(ctx);
    // 5) out-proj + residual
    gemm_nt_mma<2><<<dim3(E / 128, Mrows / 128), 256>>>(o, wo, x, x1,
                                                        Mrows, E, E);
    // 6) LN2
    ln_kernel<<<Mrows, 256>>>(x1, g2, b2, h2);
    // 7) FFN up + exact GELU
    gemm_nt_mma<1><<<dim3(Ff / 128, Mrows / 128), 256>>>(h2, w1, nullptr, f1,
                                                         Mrows, Ff, E);
    // 8) FFN down + residual -> output
    gemm_nt_mma<2><<<dim3(E / 128, Mrows / 128), 256>>>(f1, w2, x1, out,
                                                        Mrows, E, Ff);
}

// round 13
// speedup vs baseline: 1.7549x; 1.2938x over previous
#include <cuda_runtime.h>
#include <cuda_bf16.h>
#include <cstdint>
#include <math.h>

// Problem shape (fixed by the dataset instance)
constexpr int Bb = 2, Ts = 2048, E = 1024, Hh = 16, Dd = 64, Ff = 4096;
constexpr int Mrows = Bb * Ts;   // 4096

// ---------------- scratch (device globals; no allocation allowed) ----------
__device__ float g_h  [(size_t)Mrows * E];
__device__ float g_proj[(size_t)Mrows * 3 * E];
__device__ float g_q  [(size_t)Mrows * E];
__device__ float g_k  [(size_t)Mrows * E];
__device__ float g_v  [(size_t)Mrows * E];
__device__ float g_o  [(size_t)Mrows * E];
__device__ float g_x1 [(size_t)Mrows * E];
__device__ float g_h2 [(size_t)Mrows * E];
__device__ float g_f1 [(size_t)Mrows * Ff];

// ---------------- LayerNorm: one block per row ------------------------------
__global__ void __launch_bounds__(256) ln_kernel(
    const float* __restrict__ x, const float* __restrict__ g,
    const float* __restrict__ bta, float* __restrict__ out)
{
    int row = blockIdx.x;
    const float* xr = x + (size_t)row * E;
    float s = 0.f, s2 = 0.f;
    for (int i = threadIdx.x; i < E; i += 256) {
        float v = xr[i];
        s += v; s2 += v * v;
    }
    #pragma unroll
    for (int o = 16; o; o >>= 1) {
        s  += __shfl_xor_sync(0xffffffffu, s,  o);
        s2 += __shfl_xor_sync(0xffffffffu, s2, o);
    }
    __shared__ float sh[2][8];
    int w = threadIdx.x >> 5, ln = threadIdx.x & 31;
    if (ln == 0) { sh[0][w] = s; sh[1][w] = s2; }
    __syncthreads();
    float ts = 0.f, ts2 = 0.f;
    #pragma unroll
    for (int i = 0; i < 8; i++) { ts += sh[0][i]; ts2 += sh[1][i]; }
    float mu  = ts  * (1.f / E);
    float var = ts2 * (1.f / E) - mu * mu;
    float rs  = rsqrtf(var + 1e-5f);
    float* orow = out + (size_t)row * E;
    for (int i = threadIdx.x; i < E; i += 256)
        orow[i] = (xr[i] - mu) * rs * g[i] + bta[i];
}

// ---------------- RoPE split: proj -> q,k (roped, [B,H,T,D]) + v ------------
__global__ void __launch_bounds__(256) rope_kernel(const float* __restrict__ proj)
{
    int idx = blockIdx.x * 256 + threadIdx.x;
    int i = idx & 31;
    int h = (idx >> 5) & 15;
    int t = (idx >> 9) & (Ts - 1);
    int b = idx >> 20;
    if (b >= Bb) return;
    size_t base = ((size_t)(b * Ts + t) * 3) * E + (size_t)h * Dd + 2 * i;
    float qr = proj[base],         qi = proj[base + 1];
    float kr = proj[base + E],     ki = proj[base + E + 1];
    float vr = proj[base + 2 * E], vi = proj[base + 2 * E + 1];
    double invf = pow(10000.0, -(double)i / 32.0);
    double ang  = (double)t * invf;
    float c = (float)cos(ang), sn = (float)sin(ang);
    size_t ob = ((size_t)(b * Hh + h) * Ts + t) * Dd + 2 * i;
    g_q[ob]     = qr * c - qi * sn;
    g_q[ob + 1] = qr * sn + qi * c;
    g_k[ob]     = kr * c - ki * sn;
    g_k[ob + 1] = kr * sn + ki * c;
    g_v[ob]     = vr;
    g_v[ob + 1] = vi;
}

// ---------------- Sliding-window attention (flash-style, dedup exp) ---------
constexpr int QT = 32, KC = 32;

__global__ void __launch_bounds__(256) attn_kernel(const int* __restrict__ ctx)
{
    __shared__ float qs[QT][68];
    __shared__ float ks[KC][68];
    __shared__ float vs[KC][68];
    __shared__ float sc[QT][33];   // probabilities p

    int W  = *ctx;
    int bh = blockIdx.y;
    int t0 = blockIdx.x * QT;
    const float* qb = g_q + (size_t)bh * Ts * Dd;
    const float* kb = g_k + (size_t)bh * Ts * Dd;
    const float* vb = g_v + (size_t)bh * Ts * Dd;
    int tid = threadIdx.x;

    // Load Q tile (32 x 64 floats)
    {
        int c = tid & 15, r0 = tid >> 4;
        #pragma unroll
        for (int rr = 0; rr < 2; rr++) {
            int r = r0 + rr * 16;
            float4 v4 = *(const float4*)(qb + (size_t)(t0 + r) * Dd + c * 4);
            *(float4*)(&qs[r][c * 4]) = v4;
        }
    }

    int qi = tid >> 3, l8 = tid & 7;
    int t  = t0 + qi;
    int d0 = l8 * 8;
    unsigned gmask = 0xFFu << (((tid & 31) >> 3) << 3);  // 8-lane group mask
    float m = -1e30f, l = 0.f;
    float acc[8];
    #pragma unroll
    for (int dd = 0; dd < 8; dd++) acc[dd] = 0.f;

    int s_lo = t0 - W + 1; if (s_lo < 0) s_lo = 0;
    int s_hi = t0 + QT - 1; if (s_hi > Ts - 1) s_hi = Ts - 1;

    for (int cs = s_lo; cs <= s_hi; cs += KC) {
        __syncthreads();
        {
            int c = tid & 15, r = tid >> 4;
            #pragma unroll
            for (int rr = 0; rr < 2; rr++) {
                int r2 = r + rr * 16;
                int s = cs + r2;
                float4 kv = make_float4(0.f, 0.f, 0.f, 0.f), vv = kv;
                if (s <= s_hi) {
                    kv = *(const float4*)(kb + (size_t)s * Dd + c * 4);
                    vv = *(const float4*)(vb + (size_t)s * Dd + c * 4);
                }
                *(float4*)(&ks[r2][c * 4]) = kv;
                *(float4*)(&vs[r2][c * 4]) = vv;
            }
        }
        __syncthreads();

        // scores: this thread owns keys jj = l8 + 8*kk
        float dot[4];
        #pragma unroll
        for (int kk = 0; kk < 4; kk++) dot[kk] = 0.f;
        #pragma unroll
        for (int d4 = 0; d4 < 16; d4++) {
            float4 qv = *(const float4*)(&qs[qi][d4 * 4]);
            #pragma unroll
            for (int kk = 0; kk < 4; kk++) {
                float4 kv = *(const float4*)(&ks[l8 + kk * 8][d4 * 4]);
                dot[kk] += qv.x * kv.x + qv.y * kv.y + qv.z * kv.z + qv.w * kv.w;
            }
        }
        float sval[4];
        float lm = -1e30f;
        #pragma unroll
        for (int kk = 0; kk < 4; kk++) {
            int s = cs + l8 + kk * 8;
            bool valid = (s <= t) && (t - s < W) && (s <= s_hi);
            sval[kk] = valid ? dot[kk] * 0.125f : -1e30f;
            lm = fmaxf(lm, sval[kk]);
        }
        // group max (8 lanes per query, contiguous in warp)
        lm = fmaxf(lm, __shfl_xor_sync(0xffffffffu, lm, 1));
        lm = fmaxf(lm, __shfl_xor_sync(0xffffffffu, lm, 2));
        lm = fmaxf(lm, __shfl_xor_sync(0xffffffffu, lm, 4));

        if (lm > -1e29f) {
            float nm   = fmaxf(m, lm);
            float corr = __expf(m - nm);
            float ls = 0.f;
            #pragma unroll
            for (int kk = 0; kk < 4; kk++) {
                float p = (sval[kk] > -1e29f) ? __expf(sval[kk] - nm) : 0.f;
                sc[qi][l8 + kk * 8] = p;
                ls += p;
            }
            ls += __shfl_xor_sync(gmask, ls, 1);
            ls += __shfl_xor_sync(gmask, ls, 2);
            ls += __shfl_xor_sync(gmask, ls, 4);
            __syncwarp(gmask);
            l = l * corr + ls;
            #pragma unroll
            for (int dd = 0; dd < 8; dd++) acc[dd] *= corr;
            #pragma unroll
            for (int j = 0; j < KC; j++) {
                float p = sc[qi][j];
                float4 v0 = *(const float4*)(&vs[j][d0]);
                float4 v1 = *(const float4*)(&vs[j][d0 + 4]);
                acc[0] += p * v0.x; acc[1] += p * v0.y;
                acc[2] += p * v0.z; acc[3] += p * v0.w;
                acc[4] += p * v1.x; acc[5] += p * v1.y;
                acc[6] += p * v1.z; acc[7] += p * v1.w;
            }
            m = nm;
        }
    }

    float inv = 1.f / l;
    int b = bh >> 4, h = bh & 15;
    float* op = g_o + ((size_t)(b * Ts + t) * Hh + h) * Dd + d0;
    #pragma unroll
    for (int dd = 0; dd < 8; dd++) op[dd] = acc[dd] * inv;
}

// ---------------- Tensor-core GEMM (NT), bf16x3 split, ldmatrix loads -------
// C[m,n] = epi( sum_k A[m,k]*B[n,k] [+ R[m,n]] )
// 128x128 tile, BK=16, 256 threads (8 warps, 2x4), 64x32 warp tile.
// EPI: 0=none, 1=exact GELU, 2=residual add
constexpr int BK   = 16;
constexpr int LDSB = BK + 8;   // bf16 row stride (24 elems = 48B, 16B-aligned)

__device__ __forceinline__ uint32_t pack_bf2(__nv_bfloat16 lo, __nv_bfloat16 hi)
{
    uint16_t l = *reinterpret_cast<uint16_t*>(&lo);
    uint16_t h = *reinterpret_cast<uint16_t*>(&hi);
    return ((uint32_t)h << 16) | l;
}

__device__ __forceinline__ uint32_t smem_u32(const void* p) {
    uint32_t a;
    asm("{ .reg .u64 t; cvta.to.shared.u64 t, %1; cvt.u32.u64 %0, t; }"
        : "=r"(a) : "l"(p));
    return a;
}

#define MMA_BF16(c, a0, a1, a2, a3, b0, b1)                                   \
    asm volatile(                                                             \
        "mma.sync.aligned.m16n8k16.row.col.f32.bf16.bf16.f32 "                \
        "{%0,%1,%2,%3}, {%4,%5,%6,%7}, {%8,%9}, {%0,%1,%2,%3};\n"             \
        : "+f"(c[0]), "+f"(c[1]), "+f"(c[2]), "+f"(c[3])                      \
        : "r"(a0), "r"(a1), "r"(a2), "r"(a3), "r"(b0), "r"(b1))

#define LDSM_X4(r0, r1, r2, r3, a)                                            \
    asm volatile(                                                             \
        "ldmatrix.sync.aligned.m8n8.x4.shared.b16 {%0,%1,%2,%3}, [%4];"       \
        : "=r"(r0), "=r"(r1), "=r"(r2), "=r"(r3) : "r"(a))

template <int EPI>
__global__ void __launch_bounds__(256) gemm_nt_mma(
    const float* __restrict__ A, const float* __restrict__ Bw,
    const float* __restrict__ R, float* __restrict__ C,
    int Mn, int Nn, int Kn)
{
    __shared__ __nv_bfloat16 As[2][2][128 * LDSB];  // [buf][hi=0/lo=1]
    __shared__ __nv_bfloat16 Bs[2][2][128 * LDSB];

    int tid  = threadIdx.x;
    int warp = tid >> 5, lane = tid & 31;
    int wm = warp >> 2, wn = warp & 3;       // 2 x 4 warp grid

    int bm = blockIdx.y * 128, bn = blockIdx.x * 128;

    // gmem staging: each thread loads 8 floats of A and 8 of B per k-step
    int ldrow = tid >> 1;
    int ldcol = (tid & 1) * 8;
    const float* Ag = A  + (size_t)(bm + ldrow) * Kn + ldcol;
    const float* Bg = Bw + (size_t)(bn + ldrow) * Kn + ldcol;

    // ldmatrix lane byte-offsets (within one 128*LDSB tile)
    // A tile mt (16 rows x 16 cols): m0 rows0-7 k0-7, m1 rows8-15 k0-7,
    // m2 rows0-7 k8-15, m3 rows8-15 k8-15 -> lanes 0-7/8-15 give rows,
    // lanes 16-31 repeat rows at k-offset 8 ELEMENTS.
    uint32_t offA[4];
    #pragma unroll
    for (int mt = 0; mt < 4; mt++) {
        int r = wm * 64 + mt * 16 + (lane & 15);
        offA[mt] = (uint32_t)(r * LDSB + (lane >> 4) * 8) * 2;
    }
    // B pair ntp: rows wn*32+ntp*16 .. +15 (n-major), k-halves at 0 / +8 elems
    uint32_t offB[2];
    #pragma unroll
    for (int ntp = 0; ntp < 2; ntp++) {
        int n0 = wn * 32 + ntp * 16;
        int grp = lane >> 3;                  // 0..3
        int rr  = lane & 7;
        int row = n0 + (grp >> 1) * 8 + rr;   // grp 0,1 -> n0.., grp 2,3 -> n0+8..
        int col = (grp & 1) * 8;              // odd groups take k8-15 half
        offB[ntp] = (uint32_t)(row * LDSB + col) * 2;
    }
    uint32_t baseAs = smem_u32(&As[0][0][0]);
    uint32_t baseBs = smem_u32(&Bs[0][0][0]);
    constexpr uint32_t TILEB = 128 * LDSB * 2;   // bytes per tile

    float acc[4][4][4];
    #pragma unroll
    for (int i = 0; i < 4; i++)
        #pragma unroll
        for (int j = 0; j < 4; j++)
            #pragma unroll
            for (int c = 0; c < 4; c++) acc[i][j][c] = 0.f;

    float ra[8], rb[8];

    auto fetch = [&](int k0) {
        *(float4*)(ra)     = *(const float4*)(Ag + k0);
        *(float4*)(ra + 4) = *(const float4*)(Ag + k0 + 4);
        *(float4*)(rb)     = *(const float4*)(Bg + k0);
        *(float4*)(rb + 4) = *(const float4*)(Bg + k0 + 4);
    };

    auto stage = [&](int buf) {
        uint32_t ah[4], al[4], bh[4], bl[4];
        #pragma unroll
        for (int i = 0; i < 4; i++) {
            float a0 = ra[2 * i], a1 = ra[2 * i + 1];
            __nv_bfloat16 h0 = __float2bfloat16(a0);
            __nv_bfloat16 h1 = __float2bfloat16(a1);
            __nv_bfloat16 l0 = __float2bfloat16(a0 - __bfloat162float(h0));
            __nv_bfloat16 l1 = __float2bfloat16(a1 - __bfloat162float(h1));
            ah[i] = pack_bf2(h0, h1);
            al[i] = pack_bf2(l0, l1);
            float b0 = rb[2 * i], b1 = rb[2 * i + 1];
            __nv_bfloat16 p0 = __float2bfloat16(b0);
            __nv_bfloat16 p1 = __float2bfloat16(b1);
            __nv_bfloat16 q0 = __float2bfloat16(b0 - __bfloat162float(p0));
            __nv_bfloat16 q1 = __float2bfloat16(b1 - __bfloat162float(p1));
            bh[i] = pack_bf2(p0, p1);
            bl[i] = pack_bf2(q0, q1);
        }
        int off = ldrow * LDSB + ldcol;
        *(uint4*)(&As[buf][0][off]) = make_uint4(ah[0], ah[1], ah[2], ah[3]);
        *(uint4*)(&As[buf][1][off]) = make_uint4(al[0], al[1], al[2], al[3]);
        *(uint4*)(&Bs[buf][0][off]) = make_uint4(bh[0], bh[1], bh[2], bh[3]);
        *(uint4*)(&Bs[buf][1][off]) = make_uint4(bl[0], bl[1], bl[2], bl[3]);
    };

    int nk = Kn / BK;
    fetch(0);
    stage(0);
    int buf = 0;

    for (int ks = 0; ks < nk; ks++) {
        __syncthreads();
        if (ks + 1 < nk) fetch((ks + 1) * BK);

        uint32_t aHi = baseAs + (uint32_t)(buf * 2 + 0) * TILEB;
        uint32_t aLo = baseAs + (uint32_t)(buf * 2 + 1) * TILEB;
        uint32_t bHi = baseBs + (uint32_t)(buf * 2 + 0) * TILEB;
        uint32_t bLo = baseBs + (uint32_t)(buf * 2 + 1) * TILEB;

        // A fragments for 4 m-tiles (hi and lo) via ldmatrix.x4
        uint32_t afh[4][4], afl[4][4];
        #pragma unroll
        for (int mt = 0; mt < 4; mt++) {
            LDSM_X4(afh[mt][0], afh[mt][1], afh[mt][2], afh[mt][3],
                    aHi + offA[mt]);
            LDSM_X4(afl[mt][0], afl[mt][1], afl[mt][2], afl[mt][3],
                    aLo + offA[mt]);
        }
        // B fragments for 4 n-tiles via 2 ldmatrix.x4 per precision
        uint32_t bfh[4][2], bfl[4][2];
        #pragma unroll
        for (int ntp = 0; ntp < 2; ntp++) {
            LDSM_X4(bfh[ntp * 2][0], bfh[ntp * 2][1],
                    bfh[ntp * 2 + 1][0], bfh[ntp * 2 + 1][1],
                    bHi + offB[ntp]);
            LDSM_X4(bfl[ntp * 2][0], bfl[ntp * 2][1],
                    bfl[ntp * 2 + 1][0], bfl[ntp * 2 + 1][1],
                    bLo + offB[ntp]);
        }

        #pragma unroll
        for (int nt = 0; nt < 4; nt++) {
            #pragma unroll
            for (int mt = 0; mt < 4; mt++) {
                MMA_BF16(acc[mt][nt], afh[mt][0], afh[mt][1], afh[mt][2],
                         afh[mt][3], bfh[nt][0], bfh[nt][1]);
                MMA_BF16(acc[mt][nt], afh[mt][0], afh[mt][1], afh[mt][2],
                         afh[mt][3], bfl[nt][0], bfl[nt][1]);
                MMA_BF16(acc[mt][nt], afl[mt][0], afl[mt][1], afl[mt][2],
                         afl[mt][3], bfh[nt][0], bfh[nt][1]);
            }
        }

        if (ks + 1 < nk) { stage(buf ^ 1); buf ^= 1; }
    }

    // Epilogue
    int g  = lane >> 2, cq = lane & 3;
    #pragma unroll
    for (int mt = 0; mt < 4; mt++) {
        #pragma unroll
        for (int half = 0; half < 2; half++) {
            int r = bm + wm * 64 + mt * 16 + g + half * 8;
            #pragma unroll
            for (int nt = 0; nt < 4; nt++) {
                int ncol = bn + wn * 32 + nt * 8 + 2 * cq;
                float v0 = acc[mt][nt][half * 2 + 0];
                float v1 = acc[mt][nt][half * 2 + 1];
                if (EPI == 1) {
                    v0 = 0.5f * v0 * (1.f + erff(v0 * 0.70710678118654752f));
                    v1 = 0.5f * v1 * (1.f + erff(v1 * 0.70710678118654752f));
                }
                if (EPI == 2) {
                    float2 rv = *(const float2*)(R + (size_t)r * Nn + ncol);
                    v0 += rv.x; v1 += rv.y;
                }
                *(float2*)(C + (size_t)r * Nn + ncol) = make_float2(v0, v1);
            }
        }
    }
}

// ---------------- launch ----------------------------------------------------
extern "C" void kernel_launch(void* const* d_in, const int* in_sizes, int n_in,
                              void* d_out, int out_size)
{
    (void)in_sizes; (void)n_in; (void)out_size;
    const float* x    = (const float*)d_in[0];
    const float* wqkv = (const float*)d_in[1];
    const float* wo   = (const float*)d_in[2];
    const float* g1   = (const float*)d_in[3];
    const float* b1   = (const float*)d_in[4];
    const float* g2   = (const float*)d_in[5];
    const float* b2   = (const float*)d_in[6];
    const float* w1   = (const float*)d_in[7];
    const float* w2   = (const float*)d_in[8];
    const int*   ctx  = (const int*)  d_in[9];
    float* out = (float*)d_out;

    float *h, *proj, *o, *x1, *h2, *f1;
    cudaGetSymbolAddress((void**)&h,    g_h);
    cudaGetSymbolAddress((void**)&proj, g_proj);
    cudaGetSymbolAddress((void**)&o,    g_o);
    cudaGetSymbolAddress((void**)&x1,   g_x1);
    cudaGetSymbolAddress((void**)&h2,   g_h2);
    cudaGetSymbolAddress((void**)&f1,   g_f1);

    // 1) LN1
    ln_kernel<<<Mrows, 256>>>(x, g1, b1, h);
    // 2) QKV projection
    gemm_nt_mma<0><<<dim3(3 * E / 128, Mrows / 128), 256>>>(h, wqkv, nullptr,
                                                            proj, Mrows, 3 * E, E);
    // 3) RoPE + split
    rope_kernel<<<(Bb * Ts * Hh * 32) / 256, 256>>>(proj);
    // 4) Sliding-window attention
    attn_kernel<<<dim3(Ts / QT, Bb * Hh), 256>>>(ctx);
    // 5) out-proj + residual
    gemm_nt_mma<2><<<dim3(E / 128, Mrows / 128), 256>>>(o, wo, x, x1,
                                                        Mrows, E, E);
    // 6) LN2
    ln_kernel<<<Mrows, 256>>>(x1, g2, b2, h2);
    // 7) FFN up + exact GELU
    gemm_nt_mma<1><<<dim3(Ff / 128, Mrows / 128), 256>>>(h2, w1, nullptr, f1,
                                                         Mrows, Ff, E);
    // 8) FFN down + residual -> output
    gemm_nt_mma<2><<<dim3(E / 128, Mrows / 128), 256>>>(f1, w2, x1, out,
                                                        Mrows, E, Ff);
}

// round 17
// speedup vs baseline: 2.0775x; 1.1838x over previous
#include <cuda_runtime.h>
#include <cuda_fp16.h>
#include <cstdint>
#include <math.h>

// Problem shape (fixed by the dataset instance)
constexpr int Bb = 2, Ts = 2048, E = 1024, Hh = 16, Dd = 64, Ff = 4096;
constexpr int Mrows = Bb * Ts;   // 4096

// ---------------- scratch (device globals; no allocation allowed) ----------
__device__ float g_h  [(size_t)Mrows * E];
__device__ float g_proj[(size_t)Mrows * 3 * E];
__device__ float g_q  [(size_t)Mrows * E];
__device__ float g_k  [(size_t)Mrows * E];
__device__ float g_v  [(size_t)Mrows * E];
__device__ float g_o  [(size_t)Mrows * E];
__device__ float g_x1 [(size_t)Mrows * E];
__device__ float g_h2 [(size_t)Mrows * E];
__device__ float g_f1 [(size_t)Mrows * Ff];

// ---------------- LayerNorm: one block per row ------------------------------
__global__ void __launch_bounds__(256) ln_kernel(
    const float* __restrict__ x, const float* __restrict__ g,
    const float* __restrict__ bta, float* __restrict__ out)
{
    int row = blockIdx.x;
    const float* xr = x + (size_t)row * E;
    float s = 0.f, s2 = 0.f;
    for (int i = threadIdx.x; i < E; i += 256) {
        float v = xr[i];
        s += v; s2 += v * v;
    }
    #pragma unroll
    for (int o = 16; o; o >>= 1) {
        s  += __shfl_xor_sync(0xffffffffu, s,  o);
        s2 += __shfl_xor_sync(0xffffffffu, s2, o);
    }
    __shared__ float sh[2][8];
    int w = threadIdx.x >> 5, ln = threadIdx.x & 31;
    if (ln == 0) { sh[0][w] = s; sh[1][w] = s2; }
    __syncthreads();
    float ts = 0.f, ts2 = 0.f;
    #pragma unroll
    for (int i = 0; i < 8; i++) { ts += sh[0][i]; ts2 += sh[1][i]; }
    float mu  = ts  * (1.f / E);
    float var = ts2 * (1.f / E) - mu * mu;
    float rs  = rsqrtf(var + 1e-5f);
    float* orow = out + (size_t)row * E;
    for (int i = threadIdx.x; i < E; i += 256)
        orow[i] = (xr[i] - mu) * rs * g[i] + bta[i];
}

// ---------------- RoPE split: proj -> q,k (roped, [B,H,T,D]) + v ------------
__global__ void __launch_bounds__(256) rope_kernel(const float* __restrict__ proj)
{
    int idx = blockIdx.x * 256 + threadIdx.x;
    int i = idx & 31;
    int h = (idx >> 5) & 15;
    int t = (idx >> 9) & (Ts - 1);
    int b = idx >> 20;
    if (b >= Bb) return;
    size_t base = ((size_t)(b * Ts + t) * 3) * E + (size_t)h * Dd + 2 * i;
    float qr = proj[base],         qi = proj[base + 1];
    float kr = proj[base + E],     ki = proj[base + E + 1];
    float vr = proj[base + 2 * E], vi = proj[base + 2 * E + 1];
    double invf = pow(10000.0, -(double)i / 32.0);
    double ang  = (double)t * invf;
    float c = (float)cos(ang), sn = (float)sin(ang);
    size_t ob = ((size_t)(b * Hh + h) * Ts + t) * Dd + 2 * i;
    g_q[ob]     = qr * c - qi * sn;
    g_q[ob + 1] = qr * sn + qi * c;
    g_k[ob]     = kr * c - ki * sn;
    g_k[ob + 1] = kr * sn + ki * c;
    g_v[ob]     = vr;
    g_v[ob + 1] = vi;
}

// ---------------- Sliding-window attention (flash-style) --------------------
constexpr int QT = 32, KC = 32;

__global__ void __launch_bounds__(256) attn_kernel(const int* __restrict__ ctx)
{
    __shared__ float qs[QT][68];
    __shared__ float ks[KC][68];
    __shared__ float vs[KC][68];

    int W  = *ctx;
    int bh = blockIdx.y;
    int t0 = blockIdx.x * QT;
    const float* qb = g_q + (size_t)bh * Ts * Dd;
    const float* kb = g_k + (size_t)bh * Ts * Dd;
    const float* vb = g_v + (size_t)bh * Ts * Dd;
    int tid = threadIdx.x;

    // Load Q tile (32 x 64 floats)
    {
        int c = tid & 15, r0 = tid >> 4;
        #pragma unroll
        for (int rr = 0; rr < 2; rr++) {
            int r = r0 + rr * 16;
            float4 v4 = *(const float4*)(qb + (size_t)(t0 + r) * Dd + c * 4);
            *(float4*)(&qs[r][c * 4]) = v4;
        }
    }

    int qi = tid >> 3, l8 = tid & 7;
    int lane = tid & 31;
    int t  = t0 + qi;
    int d0 = l8 * 8;
    int lbase = lane & 24;                       // group base lane in warp
    unsigned gmask = 0xFFu << lbase;             // 8-lane group mask
    float m = -1e30f, l = 0.f;
    float acc[8];
    #pragma unroll
    for (int dd = 0; dd < 8; dd++) acc[dd] = 0.f;

    int s_lo = t0 - W + 1; if (s_lo < 0) s_lo = 0;
    int s_hi = t0 + QT - 1; if (s_hi > Ts - 1) s_hi = Ts - 1;

    for (int cs = s_lo; cs <= s_hi; cs += KC) {
        __syncthreads();
        {
            int c = tid & 15, r = tid >> 4;
            #pragma unroll
            for (int rr = 0; rr < 2; rr++) {
                int r2 = r + rr * 16;
                int s = cs + r2;
                float4 kv = make_float4(0.f, 0.f, 0.f, 0.f), vv = kv;
                if (s <= s_hi) {
                    kv = *(const float4*)(kb + (size_t)s * Dd + c * 4);
                    vv = *(const float4*)(vb + (size_t)s * Dd + c * 4);
                }
                *(float4*)(&ks[r2][c * 4]) = kv;
                *(float4*)(&vs[r2][c * 4]) = vv;
            }
        }
        __syncthreads();

        // scores: this thread owns keys jj = l8 + 8*kk
        float dot[4];
        #pragma unroll
        for (int kk = 0; kk < 4; kk++) dot[kk] = 0.f;
        #pragma unroll
        for (int d4 = 0; d4 < 16; d4++) {
            float4 qv = *(const float4*)(&qs[qi][d4 * 4]);
            #pragma unroll
            for (int kk = 0; kk < 4; kk++) {
                float4 kv = *(const float4*)(&ks[l8 + kk * 8][d4 * 4]);
                dot[kk] += qv.x * kv.x + qv.y * kv.y + qv.z * kv.z + qv.w * kv.w;
            }
        }
        float sval[4];
        float lm = -1e30f;
        #pragma unroll
        for (int kk = 0; kk < 4; kk++) {
            int s = cs + l8 + kk * 8;
            bool valid = (s <= t) && (t - s < W) && (s <= s_hi);
            sval[kk] = valid ? dot[kk] * 0.125f : -1e30f;
            lm = fmaxf(lm, sval[kk]);
        }
        // group max (8 lanes per query, contiguous in warp)
        lm = fmaxf(lm, __shfl_xor_sync(0xffffffffu, lm, 1));
        lm = fmaxf(lm, __shfl_xor_sync(0xffffffffu, lm, 2));
        lm = fmaxf(lm, __shfl_xor_sync(0xffffffffu, lm, 4));

        if (lm > -1e29f) {     // group-uniform condition
            float nm   = fmaxf(m, lm);
            float corr = __expf(m - nm);
            float pexp[4];
            float ls = 0.f;
            #pragma unroll
            for (int kk = 0; kk < 4; kk++) {
                float p = (sval[kk] > -1e29f) ? __expf(sval[kk] - nm) : 0.f;
                pexp[kk] = p;
                ls += p;
            }
            ls += __shfl_xor_sync(gmask, ls, 1);
            ls += __shfl_xor_sync(gmask, ls, 2);
            ls += __shfl_xor_sync(gmask, ls, 4);
            l = l * corr + ls;
            #pragma unroll
            for (int dd = 0; dd < 8; dd++) acc[dd] *= corr;
            #pragma unroll
            for (int j = 0; j < KC; j++) {
                float p = __shfl_sync(gmask, pexp[j >> 3], lbase | (j & 7));
                float4 v0 = *(const float4*)(&vs[j][d0]);
                float4 v1 = *(const float4*)(&vs[j][d0 + 4]);
                acc[0] += p * v0.x; acc[1] += p * v0.y;
                acc[2] += p * v0.z; acc[3] += p * v0.w;
                acc[4] += p * v1.x; acc[5] += p * v1.y;
                acc[6] += p * v1.z; acc[7] += p * v1.w;
            }
            m = nm;
        }
    }

    float inv = 1.f / l;
    int b = bh >> 4, h = bh & 15;
    float* op = g_o + ((size_t)(b * Ts + t) * Hh + h) * Dd + d0;
    #pragma unroll
    for (int dd = 0; dd < 8; dd++) op[dd] = acc[dd] * inv;
}

// ---------------- Tensor-core GEMM (NT), single-pass fp16, ldmatrix ---------
// C[m,n] = epi( sum_k A[m,k]*B[n,k] [+ R[m,n]] )
// 128x128 tile, BK=16, 256 threads (8 warps, 2x4), 64x32 warp tile.
// EPI: 0=none, 1=exact GELU, 2=residual add
constexpr int BK   = 16;
constexpr int LDSB = BK + 8;   // fp16 row stride (24 elems = 48B, 16B-aligned)

__device__ __forceinline__ uint32_t smem_u32(const void* p) {
    uint32_t a;
    asm("{ .reg .u64 t; cvta.to.shared.u64 t, %1; cvt.u32.u64 %0, t; }"
        : "=r"(a) : "l"(p));
    return a;
}

#define MMA_F16(c, a0, a1, a2, a3, b0, b1)                                    \
    asm volatile(                                                             \
        "mma.sync.aligned.m16n8k16.row.col.f32.f16.f16.f32 "                  \
        "{%0,%1,%2,%3}, {%4,%5,%6,%7}, {%8,%9}, {%0,%1,%2,%3};\n"             \
        : "+f"(c[0]), "+f"(c[1]), "+f"(c[2]), "+f"(c[3])                      \
        : "r"(a0), "r"(a1), "r"(a2), "r"(a3), "r"(b0), "r"(b1))

#define LDSM_X4(r0, r1, r2, r3, a)                                            \
    asm volatile(                                                             \
        "ldmatrix.sync.aligned.m8n8.x4.shared.b16 {%0,%1,%2,%3}, [%4];"       \
        : "=r"(r0), "=r"(r1), "=r"(r2), "=r"(r3) : "r"(a))

template <int EPI>
__global__ void __launch_bounds__(256) gemm_nt_mma(
    const float* __restrict__ A, const float* __restrict__ Bw,
    const float* __restrict__ R, float* __restrict__ C,
    int Mn, int Nn, int Kn)
{
    __shared__ __half As[2][128 * LDSB];
    __shared__ __half Bs[2][128 * LDSB];

    int tid  = threadIdx.x;
    int warp = tid >> 5, lane = tid & 31;
    int wm = warp >> 2, wn = warp & 3;       // 2 x 4 warp grid

    int bm = blockIdx.y * 128, bn = blockIdx.x * 128;

    // gmem staging: each thread loads 8 floats of A and 8 of B per k-step
    int ldrow = tid >> 1;
    int ldcol = (tid & 1) * 8;
    const float* Ag = A  + (size_t)(bm + ldrow) * Kn + ldcol;
    const float* Bg = Bw + (size_t)(bn + ldrow) * Kn + ldcol;

    // ldmatrix lane byte-offsets (within one 128*LDSB tile)
    uint32_t offA[4];
    #pragma unroll
    for (int mt = 0; mt < 4; mt++) {
        int r = wm * 64 + mt * 16 + (lane & 15);
        offA[mt] = (uint32_t)(r * LDSB + (lane >> 4) * 8) * 2;
    }
    uint32_t offB[2];
    #pragma unroll
    for (int ntp = 0; ntp < 2; ntp++) {
        int n0 = wn * 32 + ntp * 16;
        int grp = lane >> 3;
        int rr  = lane & 7;
        int row = n0 + (grp >> 1) * 8 + rr;
        int col = (grp & 1) * 8;
        offB[ntp] = (uint32_t)(row * LDSB + col) * 2;
    }
    uint32_t baseAs = smem_u32(&As[0][0]);
    uint32_t baseBs = smem_u32(&Bs[0][0]);
    constexpr uint32_t TILEB = 128 * LDSB * 2;   // bytes per tile

    float acc[4][4][4];
    #pragma unroll
    for (int i = 0; i < 4; i++)
        #pragma unroll
        for (int j = 0; j < 4; j++)
            #pragma unroll
            for (int c = 0; c < 4; c++) acc[i][j][c] = 0.f;

    float ra[8], rb[8];

    auto fetch = [&](int k0) {
        *(float4*)(ra)     = *(const float4*)(Ag + k0);
        *(float4*)(ra + 4) = *(const float4*)(Ag + k0 + 4);
        *(float4*)(rb)     = *(const float4*)(Bg + k0);
        *(float4*)(rb + 4) = *(const float4*)(Bg + k0 + 4);
    };

    auto stage = [&](int buf) {
        uint32_t ah[4], bh[4];
        #pragma unroll
        for (int i = 0; i < 4; i++) {
            __half2 a2 = __floats2half2_rn(ra[2 * i], ra[2 * i + 1]);
            __half2 b2 = __floats2half2_rn(rb[2 * i], rb[2 * i + 1]);
            ah[i] = *reinterpret_cast<uint32_t*>(&a2);
            bh[i] = *reinterpret_cast<uint32_t*>(&b2);
        }
        int off = ldrow * LDSB + ldcol;
        *(uint4*)(&As[buf][off]) = make_uint4(ah[0], ah[1], ah[2], ah[3]);
        *(uint4*)(&Bs[buf][off]) = make_uint4(bh[0], bh[1], bh[2], bh[3]);
    };

    int nk = Kn / BK;
    fetch(0);
    stage(0);
    int buf = 0;

    for (int ks = 0; ks < nk; ks++) {
        __syncthreads();
        if (ks + 1 < nk) fetch((ks + 1) * BK);

        uint32_t aT = baseAs + (uint32_t)buf * TILEB;
        uint32_t bT = baseBs + (uint32_t)buf * TILEB;

        uint32_t af[4][4];
        #pragma unroll
        for (int mt = 0; mt < 4; mt++)
            LDSM_X4(af[mt][0], af[mt][1], af[mt][2], af[mt][3], aT + offA[mt]);

        uint32_t bf[4][2];
        #pragma unroll
        for (int ntp = 0; ntp < 2; ntp++)
            LDSM_X4(bf[ntp * 2][0], bf[ntp * 2][1],
                    bf[ntp * 2 + 1][0], bf[ntp * 2 + 1][1], bT + offB[ntp]);

        #pragma unroll
        for (int nt = 0; nt < 4; nt++)
            #pragma unroll
            for (int mt = 0; mt < 4; mt++)
                MMA_F16(acc[mt][nt], af[mt][0], af[mt][1], af[mt][2],
                        af[mt][3], bf[nt][0], bf[nt][1]);

        if (ks + 1 < nk) { stage(buf ^ 1); buf ^= 1; }
    }

    // Epilogue
    int g  = lane >> 2, cq = lane & 3;
    #pragma unroll
    for (int mt = 0; mt < 4; mt++) {
        #pragma unroll
        for (int half = 0; half < 2; half++) {
            int r = bm + wm * 64 + mt * 16 + g + half * 8;
            #pragma unroll
            for (int nt = 0; nt < 4; nt++) {
                int ncol = bn + wn * 32 + nt * 8 + 2 * cq;
                float v0 = acc[mt][nt][half * 2 + 0];
                float v1 = acc[mt][nt][half * 2 + 1];
                if (EPI == 1) {
                    v0 = 0.5f * v0 * (1.f + erff(v0 * 0.70710678118654752f));
                    v1 = 0.5f * v1 * (1.f + erff(v1 * 0.70710678118654752f));
                }
                if (EPI == 2) {
                    float2 rv = *(const float2*)(R + (size_t)r * Nn + ncol);
                    v0 += rv.x; v1 += rv.y;
                }
                *(float2*)(C + (size_t)r * Nn + ncol) = make_float2(v0, v1);
            }
        }
    }
}

// ---------------- launch ----------------------------------------------------
extern "C" void kernel_launch(void* const* d_in, const int* in_sizes, int n_in,
                              void* d_out, int out_size)
{
    (void)in_sizes; (void)n_in; (void)out_size;
    const float* x    = (const float*)d_in[0];
    const float* wqkv = (const float*)d_in[1];
    const float* wo   = (const float*)d_in[2];
    const float* g1   = (const float*)d_in[3];
    const float* b1   = (const float*)d_in[4];
    const float* g2   = (const float*)d_in[5];
    const float* b2   = (const float*)d_in[6];
    const float* w1   = (const float*)d_in[7];
    const float* w2   = (const float*)d_in[8];
    const int*   ctx  = (const int*)  d_in[9];
    float* out = (float*)d_out;

    float *h, *proj, *o, *x1, *h2, *f1;
    cudaGetSymbolAddress((void**)&h,    g_h);
    cudaGetSymbolAddress((void**)&proj, g_proj);
    cudaGetSymbolAddress((void**)&o,    g_o);
    cudaGetSymbolAddress((void**)&x1,   g_x1);
    cudaGetSymbolAddress((void**)&h2,   g_h2);
    cudaGetSymbolAddress((void**)&f1,   g_f1);

    // 1) LN1
    ln_kernel<<<Mrows, 256>>>(x, g1, b1, h);
    // 2) QKV projection
    gemm_nt_mma<0><<<dim3(3 * E / 128, Mrows / 128), 256>>>(h, wqkv, nullptr,
                                                            proj, Mrows, 3 * E, E);
    // 3) RoPE + split
    rope_kernel<<<(Bb * Ts * Hh * 32) / 256, 256>>>(proj);
    // 4) Sliding-window attention
    attn_kernel<<<dim3(Ts / QT, Bb * Hh), 256>>>(ctx);
    // 5) out-proj + residual
    gemm_nt_mma<2><<<dim3(E / 128, Mrows / 128), 256>>>(o, wo, x, x1,
                                                        Mrows, E, E);
    // 6) LN2
    ln_kernel<<<Mrows, 256>>>(x1, g2, b2, h2);
    // 7) FFN up + exact GELU
    gemm_nt_mma<1><<<dim3(Ff / 128, Mrows / 128), 256>>>(h2, w1, nullptr, f1,
                                                         Mrows, Ff, E);
    // 8) FFN down + residual -> output
    gemm_nt_mma<2><<<dim3(E / 128, Mrows / 128), 256>>>(f1, w2, x1, out,
                                                        Mrows, E, Ff);
}